// round 15
// baseline (speedup 1.0000x reference)
#include <cuda_runtime.h>
#include <cuda_bf16.h>
#include <cstdint>

#define NUM_CLASSES 8
#define EPS_SN 1e-5f
#define CCH 8
#define PY  4

// ---------------- scratch (device globals; no allocation allowed) ------------
__device__ float g_bufA[67108864];
__device__ float g_bufB[67108864];
__device__ __nv_bfloat16 g_P0h[67108864], g_P0l[67108864];  // NHWC ping
__device__ __nv_bfloat16 g_P1h[67108864], g_P1l[67108864];  // NHWC pong
__device__ __nv_bfloat16 g_Wh[4194304], g_Wl[4194304];      // all convs, offset
__device__ float g_stats[16384];

// ---------------- warp-MMA helpers (family-compatible: sm_80+) ----------------
__device__ __forceinline__ uint32_t smem_u32(const void* p) {
    uint32_t a;
    asm("{ .reg .u64 t; cvta.to.shared.u64 t, %1; cvt.u32.u64 %0, t; }" : "=r"(a) : "l"(p));
    return a;
}
__device__ __forceinline__ void ldsm4(uint32_t& r0, uint32_t& r1, uint32_t& r2,
                                      uint32_t& r3, uint32_t a) {
    asm volatile("ldmatrix.sync.aligned.m8n8.x4.shared.b16 {%0,%1,%2,%3}, [%4];"
                 : "=r"(r0), "=r"(r1), "=r"(r2), "=r"(r3) : "r"(a));
}
__device__ __forceinline__ void mma16816(float* c, uint32_t a0, uint32_t a1,
                                         uint32_t a2, uint32_t a3,
                                         uint32_t b0, uint32_t b1) {
    asm volatile("mma.sync.aligned.m16n8k16.row.col.f32.bf16.bf16.f32 "
                 "{%0,%1,%2,%3}, {%4,%5,%6,%7}, {%8,%9}, {%0,%1,%2,%3};"
                 : "+f"(c[0]), "+f"(c[1]), "+f"(c[2]), "+f"(c[3])
                 : "r"(a0), "r"(a1), "r"(a2), "r"(a3), "r"(b0), "r"(b1));
}
__device__ __forceinline__ void cpasync16(uint32_t dst, const void* src) {
    asm volatile("cp.async.cg.shared.global [%0], [%1], 16;" :: "r"(dst), "l"(src));
}
#define CP_COMMIT() asm volatile("cp.async.commit_group;" ::: "memory")
#define CP_WAIT1()  asm volatile("cp.async.wait_group 1;" ::: "memory")
#define CP_WAIT0()  asm volatile("cp.async.wait_group 0;" ::: "memory")

// ---------------- all-weights prep (2 launches, struct by value) ---------------
struct PrepArgs {
    const float* w[4];
    long base[4];
    int Cout[4], Cpad[4], Cin[4], n[4];
};
__global__ __launch_bounds__(256) void prep_all_kernel(
    PrepArgs a, __nv_bfloat16* wh, __nv_bfloat16* wl)
{
    int z = blockIdx.y;
    int i = blockIdx.x * 256 + threadIdx.x;
    if (i >= a.n[z]) return;
    int Cpad = a.Cpad[z], Cin = a.Cin[z];
    int tap = i / (Cpad * Cin);
    int rem = i - tap * Cpad * Cin;
    int co = rem / Cin, ci = rem - co * Cin;
    float v = (co < a.Cout[z]) ? a.w[z][((size_t)co * Cin + ci) * 9 + tap] : 0.f;
    __nv_bfloat16 h = __float2bfloat16(v);
    wh[a.base[z] + i] = h;
    wl[a.base[z] + i] = __float2bfloat16(v - __bfloat162float(h));
}

// ---------------- NCHW fp32 -> NHWC bf16 hi/lo split (input x only) -----------
__global__ __launch_bounds__(256) void nchw_split_kernel(
    const float* __restrict__ in, __nv_bfloat16* __restrict__ ph,
    __nv_bfloat16* __restrict__ pl, int Cin, int H, int W, int cinBlocks)
{
    __shared__ float s[32][33];
    const int b   = blockIdx.z / cinBlocks;
    const int ci0 = (blockIdx.z % cinBlocks) << 5;
    const int y   = blockIdx.y;
    const int x0  = blockIdx.x << 5;
    const size_t chS = (size_t)H * W;
    const float* ip = in + ((size_t)(b * Cin + ci0) * H + y) * W + x0;
#pragma unroll
    for (int i = 0; i < 4; i++)
        s[threadIdx.y + 8 * i][threadIdx.x] = ip[(size_t)(threadIdx.y + 8 * i) * chS + threadIdx.x];
    __syncthreads();
    const size_t ob = ((size_t)b * H * W + (size_t)y * W + x0) * Cin + ci0;
#pragma unroll
    for (int i = 0; i < 4; i++) {
        int xl = threadIdx.y + 8 * i;
        float v = s[threadIdx.x][xl];
        __nv_bfloat16 h = __float2bfloat16(v);
        size_t a = ob + (size_t)xl * Cin + threadIdx.x;
        ph[a] = h;
        pl[a] = __float2bfloat16(v - __bfloat162float(h));
    }
}

// ---------------- warp-MMA implicit-GEMM 3x3 conv (bf16 split) -----------------
// 512 threads (16 warps). MT=128: warps 4m x 4n, warp tile 32x32.
// MT=64: warps 2m x 8n, warp tile 32x16. 2-stage cp.async double buffer.
// K rounds c-outer / tap-inner for L2 reuse.
template<int MT>
__global__ __launch_bounds__(512) void conv_mma_kernel(
    const __nv_bfloat16* __restrict__ Ph, const __nv_bfloat16* __restrict__ Pl,
    const __nv_bfloat16* __restrict__ Wh, const __nv_bfloat16* __restrict__ Wl,
    const float* __restrict__ bias, float* __restrict__ out,
    __nv_bfloat16* __restrict__ pho, __nv_bfloat16* __restrict__ plo, int mode,
    int Cin, int Cout, int H, int W, int logW, int logC)
{
    constexpr int ASZ = MT * 128;
    constexpr int STG = 2 * ASZ + 32768;
    constexpr int NT  = (MT == 128) ? 4 : 2;   // 8-px acc groups per warp
    constexpr int LOGMT = (MT == 128) ? 7 : 6;

    extern __shared__ char smraw[];
    const uint32_t sb0 = smem_u32(smraw);
    const uint32_t sb = (sb0 + 127) & ~127u;
    char* sm = smraw + (sb - sb0);

    const int tid = threadIdx.x;
    const int wid = tid >> 5, lane = tid & 31;
    const int mbase = (MT == 128) ? ((wid & 3) << 5) : ((wid & 1) << 5);
    const int nbase = (MT == 128) ? ((wid >> 2) << 5) : ((wid >> 1) << 4);

    const int p0  = blockIdx.x << 7;
    const int b   = blockIdx.y;
    const int co0 = blockIdx.z * MT;
    const int Cpad = gridDim.z * MT;
    const int HW = H * W;
    const __nv_bfloat16* PhB = Ph + (size_t)b * HW * Cin;
    const __nv_bfloat16* PlB = Pl + (size_t)b * HW * Cin;

    float acc[2][NT][4];
#pragma unroll
    for (int mt = 0; mt < 2; mt++)
#pragma unroll
        for (int nt = 0; nt < NT; nt++)
#pragma unroll
            for (int e = 0; e < 4; e++) acc[mt][nt][e] = 0.f;

    const int R = 9 << logC;
    const int c16 = tid & 7;
    const int rg  = tid >> 3;              // 0..63
    const uint32_t xorv = (uint32_t)(lane & 7) << 4;
    const int matq = lane >> 3;
    const int rowA = ((matq & 1) << 3) + (lane & 7);
    const int kbA16 = (matq >> 1) << 4;
    const int rowB = ((matq >> 1) << 3) + (lane & 7);
    const int kbB16 = (matq & 1) << 4;

    auto stage = [&](int rr) {
        const uint32_t sbStg = sb + (uint32_t)(rr & 1) * STG;
        const int c = rr / 9, tap = rr - 9 * c;
        const int dy = tap / 3 - 1, dx = tap - (tap / 3) * 3 - 1;
#pragma unroll
        for (int k = 0; k < MT / 64; k++) {
            int row = rg + (k << 6);
            uint32_t off = (uint32_t)(row << 7) + (((uint32_t)c16 << 4) ^ (((uint32_t)(row & 7)) << 4));
            size_t gA = ((size_t)tap * Cpad + co0 + row) * Cin + (c << 6) + (c16 << 3);
            cpasync16(sbStg + off,       Wh + gA);
            cpasync16(sbStg + ASZ + off, Wl + gA);
        }
#pragma unroll
        for (int k = 0; k < 2; k++) {
            int row = rg + (k << 6);
            int p = p0 + row;
            int y = p >> logW, x = p & (W - 1);
            int yy = y + dy; yy = (yy < 0) ? 1 : ((yy >= H) ? H - 2 : yy);
            int xx = x + dx; xx = (xx < 0) ? 1 : ((xx >= W) ? W - 2 : xx);
            size_t gB = (size_t)(yy * W + xx) * Cin + (c << 6) + (c16 << 3);
            uint32_t off = (uint32_t)(row << 7) + (((uint32_t)c16 << 4) ^ (((uint32_t)(row & 7)) << 4));
            cpasync16(sbStg + 2 * ASZ + off,         PhB + gB);
            cpasync16(sbStg + 2 * ASZ + 16384 + off, PlB + gB);
        }
    };

    stage(0);
    CP_COMMIT();

    for (int r = 0; r < R; r++) {
        if (r + 1 < R) { stage(r + 1); CP_COMMIT(); CP_WAIT1(); }
        else          { CP_WAIT0(); }
        __syncthreads();

        const uint32_t base = sb + (uint32_t)(r & 1) * STG;
#pragma unroll
        for (int ks = 0; ks < 4; ks++) {
            const uint32_t kb = (uint32_t)(ks << 5);
            uint32_t ah[2][4], al[2][4];
#pragma unroll
            for (int mt = 0; mt < 2; mt++) {
                int rowm = mbase + (mt << 4) + rowA;
                uint32_t ad = base + (uint32_t)(rowm << 7) + ((kb + kbA16) ^ xorv);
                ldsm4(ah[mt][0], ah[mt][1], ah[mt][2], ah[mt][3], ad);
                ldsm4(al[mt][0], al[mt][1], al[mt][2], al[mt][3], ad + ASZ);
            }
#pragma unroll
            for (int ntp = 0; ntp < NT / 2; ntp++) {
                int rown = nbase + (ntp << 4) + rowB;
                uint32_t bd = base + 2 * ASZ + (uint32_t)(rown << 7) + ((kb + kbB16) ^ xorv);
                uint32_t bh[4], bl[4];
                ldsm4(bh[0], bh[1], bh[2], bh[3], bd);
                ldsm4(bl[0], bl[1], bl[2], bl[3], bd + 16384);
#pragma unroll
                for (int mt = 0; mt < 2; mt++) {
                    float* c0 = acc[mt][ntp * 2];
                    float* c1 = acc[mt][ntp * 2 + 1];
                    mma16816(c0, ah[mt][0], ah[mt][1], ah[mt][2], ah[mt][3], bh[0], bh[1]);
                    mma16816(c0, ah[mt][0], ah[mt][1], ah[mt][2], ah[mt][3], bl[0], bl[1]);
                    mma16816(c0, al[mt][0], al[mt][1], al[mt][2], al[mt][3], bh[0], bh[1]);
                    mma16816(c1, ah[mt][0], ah[mt][1], ah[mt][2], ah[mt][3], bh[2], bh[3]);
                    mma16816(c1, ah[mt][0], ah[mt][1], ah[mt][2], ah[mt][3], bl[2], bl[3]);
                    mma16816(c1, al[mt][0], al[mt][1], al[mt][2], al[mt][3], bh[2], bh[3]);
                }
            }
        }
        __syncthreads();
    }

    if (mode) {
        // NHWC bf16 hi/lo epilogue via smem transpose (relu; Cout==Cpad)
        float* sf = (float*)sm;
#pragma unroll
        for (int mt = 0; mt < 2; mt++)
#pragma unroll
            for (int nt = 0; nt < NT; nt++)
#pragma unroll
                for (int e = 0; e < 4; e++) {
                    int px = nbase + (nt << 3) + ((lane & 3) << 1) + (e & 1);
                    int cl = mbase + (mt << 4) + (lane >> 2) + ((e >> 1) << 3);
                    sf[px * (MT + 4) + cl] = acc[mt][nt][e];
                }
        __syncthreads();
        for (int j = tid; j < 128 * MT; j += 512) {
            int cl = j & (MT - 1), px = j >> LOGMT;
            float v = fmaxf(sf[px * (MT + 4) + cl] + bias[co0 + cl], 0.f);
            __nv_bfloat16 h = __float2bfloat16(v);
            size_t a = ((size_t)b * HW + p0 + px) * (size_t)Cout + co0 + cl;
            pho[a] = h;
            plo[a] = __float2bfloat16(v - __bfloat162float(h));
        }
    } else {
#pragma unroll
        for (int mt = 0; mt < 2; mt++)
#pragma unroll
            for (int hh = 0; hh < 2; hh++) {
                int co = co0 + mbase + (mt << 4) + (lane >> 2) + (hh << 3);
                if (co < Cout) {
                    float bv = bias[co];
                    float* op = out + (size_t)(b * Cout + co) * HW + p0 + nbase + ((lane & 3) << 1);
#pragma unroll
                    for (int nt = 0; nt < NT; nt++) {
                        float2 v;
                        v.x = fmaxf(acc[mt][nt][hh * 2]     + bv, 0.f);
                        v.y = fmaxf(acc[mt][nt][hh * 2 + 1] + bv, 0.f);
                        *(float2*)(op + (nt << 3)) = v;
                    }
                }
            }
    }
}

// ---------------- fused segnorm-apply + bilinear up2 + NHWC bf16 split ---------
__global__ __launch_bounds__(256) void up2norm_kernel(
    const float* __restrict__ in, const float* __restrict__ stats,
    const int* __restrict__ seg, __nv_bfloat16* __restrict__ ph,
    __nv_bfloat16* __restrict__ pl, int C, int Hin, int Win, int cgN,
    int sh, float invHW)
{
    __shared__ float s[2][32][35];
    __shared__ float rs8[32][8], muR[32][8], Ksh[32];
    const int b = blockIdx.z / cgN, ci0 = (blockIdx.z % cgN) << 5;
    const int yo = blockIdx.y, xo0 = blockIdx.x << 6;
    const int Ho = Hin * 2, Wo = Win * 2;
    const int tid = threadIdx.y * 32 + threadIdx.x;

    {
        int ch = tid >> 3, k = tid & 7;
        int bc = b * C + ci0 + ch;
        float S = stats[bc * 16 + k * 2];
        float Q = stats[bc * 16 + k * 2 + 1];
        float mu = S * invHW;
        float var = Q * invHW - mu * mu;
        float r = rsqrtf(var + EPS_SN);
        rs8[ch][k] = r;
        muR[ch][k] = mu * r;
    }
    __syncthreads();
    if (tid < 32) {
        float K = 0.f;
#pragma unroll
        for (int k = 0; k < 8; k++) K += muR[tid][k];
        Ksh[tid] = K;
    }
    __syncthreads();

    int iy = yo >> 1, y0, y1;
    float wy0, wy1;
    if (yo & 1) { y0 = iy; y1 = min(iy + 1, Hin - 1); wy0 = .75f; wy1 = .25f; }
    else        { y0 = max(iy - 1, 0); y1 = iy;       wy0 = .25f; wy1 = .75f; }
    const int xin0 = xo0 >> 1;
    const int* sp = seg + b * 4096;
    for (int i = tid; i < 2176; i += 256) {
        int r = i / 1088, rem = i - r * 1088;
        int ch = rem / 34, col = rem - ch * 34;
        int gc = min(max(xin0 - 1 + col, 0), Win - 1);
        int gr = r ? y1 : y0;
        int cls = sp[((gr >> sh) << 6) + (gc >> sh)];
        float v = in[((size_t)(b * C + ci0 + ch) * Hin + gr) * Win + gc];
        s[r][ch][col] = v * rs8[ch][cls] - Ksh[ch];
    }
    __syncthreads();
    const int tx = threadIdx.x;
    const size_t obase = ((size_t)b * Ho + yo) * Wo;
#pragma unroll
    for (int k = 0; k < 8; k++) {
        int xo = xo0 + (k << 3) + threadIdx.y;
        int lx = (xo >> 1) - xin0;
        int ca, cb;
        float wa, wb;
        if (xo & 1) { ca = lx + 1; cb = lx + 2; wa = .75f; wb = .25f; }
        else        { ca = lx;     cb = lx + 1; wa = .25f; wb = .75f; }
        float v = wy0 * (wa * s[0][tx][ca] + wb * s[0][tx][cb])
                + wy1 * (wa * s[1][tx][ca] + wb * s[1][tx][cb]);
        __nv_bfloat16 h = __float2bfloat16(v);
        size_t a = (obase + xo) * C + ci0 + tx;
        ph[a] = h;
        pl[a] = __float2bfloat16(v - __bfloat162float(h));
    }
}

// ---------------- fp32 direct conv (final 64->3) -------------------------------
template<int CBT>
__global__ __launch_bounds__(256) void conv3x3_kernel(
    const float* __restrict__ in, const float* __restrict__ wgt,
    const float* __restrict__ bias, float* __restrict__ out,
    int Cin, int Cout, int H, int W, int tilesY, int doRelu)
{
    __shared__ __align__(16) float s_in[CCH][34][34];
    __shared__ __align__(16) float s_w[CCH][9][CBT];
    const int tx = threadIdx.x, ty = threadIdx.y;
    const int tid = ty * 32 + tx;
    const int tileY = blockIdx.y % tilesY;
    const int b = blockIdx.y / tilesY;
    const int co0 = blockIdx.z * CBT;
    const int x0 = blockIdx.x * 32, y0 = tileY * 32;
    float acc[PY][CBT];
#pragma unroll
    for (int p = 0; p < PY; p++)
#pragma unroll
        for (int j = 0; j < CBT; j++) acc[p][j] = 0.f;
    const float* inB = in + (size_t)b * Cin * H * W;
    for (int cin0 = 0; cin0 < Cin; cin0 += CCH) {
        __syncthreads();
        for (int i = tid; i < CCH * 1156; i += 256) {
            int ci = i / 1156, rem = i - ci * 1156;
            int r = rem / 34, c = rem - r * 34;
            int gr = y0 - 1 + r, gc = x0 - 1 + c;
            gr = (gr < 0) ? -gr : ((gr >= H) ? 2 * H - 2 - gr : gr);
            gc = (gc < 0) ? -gc : ((gc >= W) ? 2 * W - 2 - gc : gc);
            s_in[ci][r][c] = inB[(size_t)(cin0 + ci) * H * W + gr * W + gc];
        }
        for (int i = tid; i < CCH * 9 * CBT; i += 256) {
            int ci = i / (9 * CBT), rem = i - ci * (9 * CBT);
            int k = rem / CBT, j = rem - k * CBT;
            int co = co0 + j;
            s_w[ci][k][j] = (co < Cout) ? wgt[((size_t)co * Cin + cin0 + ci) * 9 + k] : 0.f;
        }
        __syncthreads();
#pragma unroll 1
        for (int ci = 0; ci < CCH; ci++) {
            float dp[6][3];
#pragma unroll
            for (int rr = 0; rr < 6; rr++)
#pragma unroll
                for (int c = 0; c < 3; c++) dp[rr][c] = s_in[ci][ty * PY + rr][tx + c];
#pragma unroll
            for (int kr = 0; kr < 3; kr++)
#pragma unroll
                for (int kc = 0; kc < 3; kc++) {
#pragma unroll
                    for (int p = 0; p < PY; p++) {
                        float d = dp[kr + p][kc];
#pragma unroll
                        for (int j = 0; j < CBT; j++)
                            acc[p][j] = fmaf(d, s_w[ci][kr * 3 + kc][j], acc[p][j]);
                    }
                }
        }
    }
    const int x = x0 + tx, yBase = y0 + ty * PY;
#pragma unroll
    for (int p = 0; p < PY; p++) {
        int y = yBase + p;
#pragma unroll
        for (int j = 0; j < CBT; j++) {
            int co = co0 + j;
            if (co < Cout) {
                float r = acc[p][j] + bias[co];
                if (doRelu) r = fmaxf(r, 0.f);
                out[((size_t)(b * Cout + co) * H + y) * W + x] = r;
            }
        }
    }
}

// ---------------- per-class instance-norm stats --------------------------------
__global__ __launch_bounds__(256) void segnorm_stats(
    const float* __restrict__ x, const int* __restrict__ seg,
    float* __restrict__ stats, int C, int HW, int logW, int sh)
{
    const int bc = blockIdx.x, b = bc / C;
    const float* xp = x + (size_t)bc * HW;
    const int* sp = seg + b * 4096;
    const int Wm1 = (1 << logW) - 1;
    float s[8] = {0}, q[8] = {0};
    for (int i = threadIdx.x; i < HW; i += 256) {
        int h = i >> logW, wd = i & Wm1;
        int cls = sp[((h >> sh) << 6) + (wd >> sh)];
        float v = xp[i], v2 = v * v;
#pragma unroll
        for (int k = 0; k < 8; k++)
            if (cls == k) { s[k] += v; q[k] += v2; }
    }
#pragma unroll
    for (int k = 0; k < 8; k++)
#pragma unroll
        for (int o = 16; o > 0; o >>= 1) {
            s[k] += __shfl_xor_sync(0xffffffffu, s[k], o);
            q[k] += __shfl_xor_sync(0xffffffffu, q[k], o);
        }
    __shared__ float shs[8][8], shq[8][8];
    int warp = threadIdx.x >> 5, lane = threadIdx.x & 31;
    if (lane == 0)
#pragma unroll
        for (int k = 0; k < 8; k++) { shs[warp][k] = s[k]; shq[warp][k] = q[k]; }
    __syncthreads();
    if (threadIdx.x < 8) {
        float S = 0, Q = 0;
#pragma unroll
        for (int w = 0; w < 8; w++) { S += shs[w][threadIdx.x]; Q += shq[w][threadIdx.x]; }
        stats[bc * 16 + threadIdx.x * 2] = S;
        stats[bc * 16 + threadIdx.x * 2 + 1] = Q;
    }
}

// ---------------- host orchestration -------------------------------------------
static inline int ilog2i(int v) { int l = 0; while ((1 << l) < v) l++; return l; }

#define DSMEM_128 (2 * (2 * 128 * 128 + 32768) + 128)
#define DSMEM_64  (2 * (2 * 64 * 128 + 32768) + 128)

static void conv_mma(const __nv_bfloat16* pih, const __nv_bfloat16* pil,
                     const __nv_bfloat16* wh, const __nv_bfloat16* wl,
                     const float* bias, float* outF,
                     __nv_bfloat16* poh, __nv_bfloat16* pol, int mode,
                     int B, int Cin, int Cout, int H, int W) {
    int MT = (Cout > 64) ? 128 : 64;
    int Cpad = ((Cout + MT - 1) / MT) * MT;
    if (MT == 128)
        conv_mma_kernel<128><<<dim3((H * W) / 128, B, Cpad / 128), 512, DSMEM_128>>>(
            pih, pil, wh, wl, bias, outF, poh, pol, mode, Cin, Cout, H, W,
            ilog2i(W), ilog2i(Cin / 64));
    else
        conv_mma_kernel<64><<<dim3((H * W) / 128, B, Cpad / 64), 512, DSMEM_64>>>(
            pih, pil, wh, wl, bias, outF, poh, pol, mode, Cin, Cout, H, W,
            ilog2i(W), ilog2i(Cin / 64));
}

extern "C" void kernel_launch(void* const* d_in, const int* in_sizes, int n_in,
                              void* d_out, int out_size) {
    const float* x   = (const float*)d_in[0];
    const int*   seg = (const int*)  d_in[1];
    const float* W[8] = { (const float*)d_in[2],  (const float*)d_in[4],
                          (const float*)d_in[6],  (const float*)d_in[8],
                          (const float*)d_in[10], (const float*)d_in[12],
                          (const float*)d_in[14], (const float*)d_in[16] };
    const float* Bi[8] = { (const float*)d_in[3],  (const float*)d_in[5],
                           (const float*)d_in[7],  (const float*)d_in[9],
                           (const float*)d_in[11], (const float*)d_in[13],
                           (const float*)d_in[15], (const float*)d_in[17] };
    const float *wf = (const float*)d_in[18], *bf_ = (const float*)d_in[19];

    cudaFuncSetAttribute(conv_mma_kernel<128>,
                         cudaFuncAttributeMaxDynamicSharedMemorySize, DSMEM_128);
    cudaFuncSetAttribute(conv_mma_kernel<64>,
                         cudaFuncAttributeMaxDynamicSharedMemorySize, DSMEM_64);

    float *A, *Bb, *st;
    __nv_bfloat16 *p0h, *p0l, *p1h, *p1l, *wh, *wl;
    cudaGetSymbolAddress((void**)&A,   g_bufA);
    cudaGetSymbolAddress((void**)&Bb,  g_bufB);
    cudaGetSymbolAddress((void**)&st,  g_stats);
    cudaGetSymbolAddress((void**)&p0h, g_P0h);
    cudaGetSymbolAddress((void**)&p0l, g_P0l);
    cudaGetSymbolAddress((void**)&p1h, g_P1h);
    cudaGetSymbolAddress((void**)&p1l, g_P1l);
    cudaGetSymbolAddress((void**)&wh,  g_Wh);
    cudaGetSymbolAddress((void**)&wl,  g_Wl);

    const int CinA[8]  = {512, 256, 256, 256, 256, 128, 128, 64};
    const int CoutA[8] = {256, 256, 256, 256, 128, 128, 64,  64};
    long base[8];
    long off = 0;
    int CpadA[8], nA[8];
    for (int i = 0; i < 8; i++) {
        int MT = (CoutA[i] > 64) ? 128 : 64;
        CpadA[i] = ((CoutA[i] + MT - 1) / MT) * MT;
        nA[i] = 9 * CpadA[i] * CinA[i];
        base[i] = off;
        off += nA[i];
    }

    // launches 1+2: all-weight prep (activation-independent)
    for (int h = 0; h < 2; h++) {
        PrepArgs pa;
        int nmax = 0;
        for (int j = 0; j < 4; j++) {
            int i = h * 4 + j;
            pa.w[j] = W[i]; pa.base[j] = base[i];
            pa.Cout[j] = CoutA[i]; pa.Cpad[j] = CpadA[i];
            pa.Cin[j] = CinA[i]; pa.n[j] = nA[i];
            if (nA[i] > nmax) nmax = nA[i];
        }
        prep_all_kernel<<<dim3((nmax + 255) / 256, 4), 256>>>(pa, wh, wl);
    }

    // launch 3: input split; launch 4: conv1 (profiled by ncu)
    nchw_split_kernel<<<dim3(2, 64, 4 * 16), dim3(32, 8)>>>(x, p0h, p0l, 512, 64, 64, 16);
    conv_mma(p0h, p0l, wh + base[0], wl + base[0], Bi[0], A, 0, 0, 0, 4, 512, 256, 64, 64);
    segnorm_stats<<<4 * 256, 256>>>(A, seg, st, 256, 4096, 6, 0);
    up2norm_kernel<<<dim3(2, 128, 4 * 8), dim3(32, 8)>>>(A, st, seg, p1h, p1l,
                                                         256, 64, 64, 8, 0, 1.f / 4096.f);
    // stage 2 @ 128x128
    conv_mma(p1h, p1l, wh + base[1], wl + base[1], Bi[1], 0, p0h, p0l, 1, 4, 256, 256, 128, 128);
    conv_mma(p0h, p0l, wh + base[2], wl + base[2], Bi[2], 0, p1h, p1l, 1, 4, 256, 256, 128, 128);
    conv_mma(p1h, p1l, wh + base[3], wl + base[3], Bi[3], 0, p0h, p0l, 1, 4, 256, 256, 128, 128);
    conv_mma(p0h, p0l, wh + base[4], wl + base[4], Bi[4], A, 0, 0, 0, 4, 256, 128, 128, 128);
    segnorm_stats<<<4 * 128, 256>>>(A, seg, st, 128, 16384, 7, 1);
    up2norm_kernel<<<dim3(4, 256, 4 * 4), dim3(32, 8)>>>(A, st, seg, p1h, p1l,
                                                         128, 128, 128, 4, 1, 1.f / 16384.f);
    // stage 3 @ 256x256
    conv_mma(p1h, p1l, wh + base[5], wl + base[5], Bi[5], 0, p0h, p0l, 1, 4, 128, 128, 256, 256);
    conv_mma(p0h, p0l, wh + base[6], wl + base[6], Bi[6], A, 0, 0, 0, 4, 128, 64, 256, 256);
    segnorm_stats<<<4 * 64, 256>>>(A, seg, st, 64, 65536, 8, 2);
    up2norm_kernel<<<dim3(8, 512, 4 * 2), dim3(32, 8)>>>(A, st, seg, p1h, p1l,
                                                         64, 256, 256, 2, 2, 1.f / 65536.f);
    // stage 4 @ 512x512
    conv_mma(p1h, p1l, wh + base[7], wl + base[7], Bi[7], Bb, 0, 0, 0, 4, 64, 64, 512, 512);
    conv3x3_kernel<4><<<dim3(16, 16 * 4, 1), dim3(32, 8)>>>(
        Bb, wf, bf_, (float*)d_out, 64, 3, 512, 512, 16, 0);
}

// round 17
// speedup vs baseline: 1.0493x; 1.0493x over previous
#include <cuda_runtime.h>
#include <cuda_bf16.h>
#include <cstdint>

#define NUM_CLASSES 8
#define EPS_SN 1e-5f
#define CCH 8
#define PY  4

// ---------------- scratch (device globals; no allocation allowed) ------------
__device__ float g_bufA[67108864];
__device__ float g_bufB[67108864];
__device__ __nv_bfloat16 g_P0h[67108864], g_P0l[67108864];  // NHWC ping
__device__ __nv_bfloat16 g_P1h[67108864], g_P1l[67108864];  // NHWC pong
__device__ __nv_bfloat16 g_Wh[4194304], g_Wl[4194304];      // all convs, offset
__device__ float g_stats[16384];

// ---------------- warp-MMA helpers (family-compatible: sm_80+) ----------------
__device__ __forceinline__ uint32_t smem_u32(const void* p) {
    uint32_t a;
    asm("{ .reg .u64 t; cvta.to.shared.u64 t, %1; cvt.u32.u64 %0, t; }" : "=r"(a) : "l"(p));
    return a;
}
__device__ __forceinline__ void ldsm4(uint32_t& r0, uint32_t& r1, uint32_t& r2,
                                      uint32_t& r3, uint32_t a) {
    asm volatile("ldmatrix.sync.aligned.m8n8.x4.shared.b16 {%0,%1,%2,%3}, [%4];"
                 : "=r"(r0), "=r"(r1), "=r"(r2), "=r"(r3) : "r"(a));
}
__device__ __forceinline__ void mma16816(float* c, uint32_t a0, uint32_t a1,
                                         uint32_t a2, uint32_t a3,
                                         uint32_t b0, uint32_t b1) {
    asm volatile("mma.sync.aligned.m16n8k16.row.col.f32.bf16.bf16.f32 "
                 "{%0,%1,%2,%3}, {%4,%5,%6,%7}, {%8,%9}, {%0,%1,%2,%3};"
                 : "+f"(c[0]), "+f"(c[1]), "+f"(c[2]), "+f"(c[3])
                 : "r"(a0), "r"(a1), "r"(a2), "r"(a3), "r"(b0), "r"(b1));
}
__device__ __forceinline__ void cpasync16(uint32_t dst, const void* src) {
    asm volatile("cp.async.cg.shared.global [%0], [%1], 16;" :: "r"(dst), "l"(src));
}
#define CP_COMMIT() asm volatile("cp.async.commit_group;" ::: "memory")
#define CP_WAIT1()  asm volatile("cp.async.wait_group 1;" ::: "memory")
#define CP_WAIT0()  asm volatile("cp.async.wait_group 0;" ::: "memory")

// ---------------- all-weights prep (2 launches, struct by value) ---------------
struct PrepArgs {
    const float* w[4];
    long base[4];
    int Cout[4], Cpad[4], Cin[4], n[4];
};
__global__ __launch_bounds__(256) void prep_all_kernel(
    PrepArgs a, __nv_bfloat16* wh, __nv_bfloat16* wl)
{
    int z = blockIdx.y;
    int i = blockIdx.x * 256 + threadIdx.x;
    if (i >= a.n[z]) return;
    int Cpad = a.Cpad[z], Cin = a.Cin[z];
    int tap = i / (Cpad * Cin);
    int rem = i - tap * Cpad * Cin;
    int co = rem / Cin, ci = rem - co * Cin;
    float v = (co < a.Cout[z]) ? a.w[z][((size_t)co * Cin + ci) * 9 + tap] : 0.f;
    __nv_bfloat16 h = __float2bfloat16(v);
    wh[a.base[z] + i] = h;
    wl[a.base[z] + i] = __float2bfloat16(v - __bfloat162float(h));
}

// ---------------- NCHW fp32 -> NHWC bf16 hi/lo split (input x only) -----------
__global__ __launch_bounds__(256) void nchw_split_kernel(
    const float* __restrict__ in, __nv_bfloat16* __restrict__ ph,
    __nv_bfloat16* __restrict__ pl, int Cin, int H, int W, int cinBlocks)
{
    __shared__ float s[32][33];
    const int b   = blockIdx.z / cinBlocks;
    const int ci0 = (blockIdx.z % cinBlocks) << 5;
    const int y   = blockIdx.y;
    const int x0  = blockIdx.x << 5;
    const size_t chS = (size_t)H * W;
    const float* ip = in + ((size_t)(b * Cin + ci0) * H + y) * W + x0;
#pragma unroll
    for (int i = 0; i < 4; i++)
        s[threadIdx.y + 8 * i][threadIdx.x] = ip[(size_t)(threadIdx.y + 8 * i) * chS + threadIdx.x];
    __syncthreads();
    const size_t ob = ((size_t)b * H * W + (size_t)y * W + x0) * Cin + ci0;
#pragma unroll
    for (int i = 0; i < 4; i++) {
        int xl = threadIdx.y + 8 * i;
        float v = s[threadIdx.x][xl];
        __nv_bfloat16 h = __float2bfloat16(v);
        size_t a = ob + (size_t)xl * Cin + threadIdx.x;
        ph[a] = h;
        pl[a] = __float2bfloat16(v - __bfloat162float(h));
    }
}

// ---------------- warp-MMA implicit-GEMM 3x3 conv (bf16 split) -----------------
// PROVEN BEST config (R12): 256 threads (8 warps, 4m x 2n), warp tile 32x64,
// 2-stage cp.async double buffer, K rounds c-outer / tap-inner for L2 reuse.
template<int MT>
__global__ __launch_bounds__(256) void conv_mma_kernel(
    const __nv_bfloat16* __restrict__ Ph, const __nv_bfloat16* __restrict__ Pl,
    const __nv_bfloat16* __restrict__ Wh, const __nv_bfloat16* __restrict__ Wl,
    const float* __restrict__ bias, float* __restrict__ out,
    __nv_bfloat16* __restrict__ pho, __nv_bfloat16* __restrict__ plo, int mode,
    int Cin, int Cout, int H, int W, int logW, int logC)
{
    constexpr int ASZ = MT * 128;
    constexpr int STG = 2 * ASZ + 32768;
    constexpr int NT  = (MT == 128) ? 8 : 4;
    constexpr int LOGMT = (MT == 128) ? 7 : 6;

    extern __shared__ char smraw[];
    const uint32_t sb0 = smem_u32(smraw);
    const uint32_t sb = (sb0 + 127) & ~127u;
    char* sm = smraw + (sb - sb0);

    const int tid = threadIdx.x;
    const int wid = tid >> 5, lane = tid & 31;
    const int mbase = (MT == 128) ? ((wid & 3) << 5) : ((wid & 1) << 5);
    const int nbase = (MT == 128) ? ((wid >> 2) << 6) : ((wid >> 1) << 5);

    const int p0  = blockIdx.x << 7;
    const int b   = blockIdx.y;
    const int co0 = blockIdx.z * MT;
    const int Cpad = gridDim.z * MT;
    const int HW = H * W;
    const __nv_bfloat16* PhB = Ph + (size_t)b * HW * Cin;
    const __nv_bfloat16* PlB = Pl + (size_t)b * HW * Cin;

    float acc[2][NT][4];
#pragma unroll
    for (int mt = 0; mt < 2; mt++)
#pragma unroll
        for (int nt = 0; nt < NT; nt++)
#pragma unroll
            for (int e = 0; e < 4; e++) acc[mt][nt][e] = 0.f;

    const int R = 9 << logC;
    const int c16 = tid & 7;
    const int rg  = tid >> 3;             // 0..31
    const uint32_t xorv = (uint32_t)(lane & 7) << 4;
    const int matq = lane >> 3;
    const int rowA = ((matq & 1) << 3) + (lane & 7);
    const int kbA16 = (matq >> 1) << 4;
    const int rowB = ((matq >> 1) << 3) + (lane & 7);
    const int kbB16 = (matq & 1) << 4;

    auto stage = [&](int rr) {
        const uint32_t sbStg = sb + (uint32_t)(rr & 1) * STG;
        const int c = rr / 9, tap = rr - 9 * c;
        const int dy = tap / 3 - 1, dx = tap - (tap / 3) * 3 - 1;
#pragma unroll
        for (int k = 0; k < MT / 32; k++) {
            int row = rg + (k << 5);
            uint32_t off = (uint32_t)(row << 7) + (((uint32_t)c16 << 4) ^ (((uint32_t)(row & 7)) << 4));
            size_t gA = ((size_t)tap * Cpad + co0 + row) * Cin + (c << 6) + (c16 << 3);
            cpasync16(sbStg + off,       Wh + gA);
            cpasync16(sbStg + ASZ + off, Wl + gA);
        }
#pragma unroll
        for (int k = 0; k < 4; k++) {
            int row = rg + (k << 5);
            int p = p0 + row;
            int y = p >> logW, x = p & (W - 1);
            int yy = y + dy; yy = (yy < 0) ? 1 : ((yy >= H) ? H - 2 : yy);
            int xx = x + dx; xx = (xx < 0) ? 1 : ((xx >= W) ? W - 2 : xx);
            size_t gB = (size_t)(yy * W + xx) * Cin + (c << 6) + (c16 << 3);
            uint32_t off = (uint32_t)(row << 7) + (((uint32_t)c16 << 4) ^ (((uint32_t)(row & 7)) << 4));
            cpasync16(sbStg + 2 * ASZ + off,         PhB + gB);
            cpasync16(sbStg + 2 * ASZ + 16384 + off, PlB + gB);
        }
    };

    stage(0);
    CP_COMMIT();

    for (int r = 0; r < R; r++) {
        if (r + 1 < R) { stage(r + 1); CP_COMMIT(); CP_WAIT1(); }
        else          { CP_WAIT0(); }
        __syncthreads();

        const uint32_t base = sb + (uint32_t)(r & 1) * STG;
#pragma unroll
        for (int ks = 0; ks < 4; ks++) {
            const uint32_t kb = (uint32_t)(ks << 5);
            uint32_t ah[2][4], al[2][4];
#pragma unroll
            for (int mt = 0; mt < 2; mt++) {
                int rowm = mbase + (mt << 4) + rowA;
                uint32_t ad = base + (uint32_t)(rowm << 7) + ((kb + kbA16) ^ xorv);
                ldsm4(ah[mt][0], ah[mt][1], ah[mt][2], ah[mt][3], ad);
                ldsm4(al[mt][0], al[mt][1], al[mt][2], al[mt][3], ad + ASZ);
            }
#pragma unroll
            for (int ntp = 0; ntp < NT / 2; ntp++) {
                int rown = nbase + (ntp << 4) + rowB;
                uint32_t bd = base + 2 * ASZ + (uint32_t)(rown << 7) + ((kb + kbB16) ^ xorv);
                uint32_t bh[4], bl[4];
                ldsm4(bh[0], bh[1], bh[2], bh[3], bd);
                ldsm4(bl[0], bl[1], bl[2], bl[3], bd + 16384);
#pragma unroll
                for (int mt = 0; mt < 2; mt++) {
                    float* c0 = acc[mt][ntp * 2];
                    float* c1 = acc[mt][ntp * 2 + 1];
                    mma16816(c0, ah[mt][0], ah[mt][1], ah[mt][2], ah[mt][3], bh[0], bh[1]);
                    mma16816(c0, ah[mt][0], ah[mt][1], ah[mt][2], ah[mt][3], bl[0], bl[1]);
                    mma16816(c0, al[mt][0], al[mt][1], al[mt][2], al[mt][3], bh[0], bh[1]);
                    mma16816(c1, ah[mt][0], ah[mt][1], ah[mt][2], ah[mt][3], bh[2], bh[3]);
                    mma16816(c1, ah[mt][0], ah[mt][1], ah[mt][2], ah[mt][3], bl[2], bl[3]);
                    mma16816(c1, al[mt][0], al[mt][1], al[mt][2], al[mt][3], bh[2], bh[3]);
                }
            }
        }
        __syncthreads();
    }

    if (mode) {
        // NHWC bf16 hi/lo epilogue via smem transpose (relu; Cout==Cpad)
        float* sf = (float*)sm;
#pragma unroll
        for (int mt = 0; mt < 2; mt++)
#pragma unroll
            for (int nt = 0; nt < NT; nt++)
#pragma unroll
                for (int e = 0; e < 4; e++) {
                    int px = nbase + (nt << 3) + ((lane & 3) << 1) + (e & 1);
                    int cl = mbase + (mt << 4) + (lane >> 2) + ((e >> 1) << 3);
                    sf[px * (MT + 4) + cl] = acc[mt][nt][e];
                }
        __syncthreads();
        for (int j = tid; j < 128 * MT; j += 256) {
            int cl = j & (MT - 1), px = j >> LOGMT;
            float v = fmaxf(sf[px * (MT + 4) + cl] + bias[co0 + cl], 0.f);
            __nv_bfloat16 h = __float2bfloat16(v);
            size_t a = ((size_t)b * HW + p0 + px) * (size_t)Cout + co0 + cl;
            pho[a] = h;
            plo[a] = __float2bfloat16(v - __bfloat162float(h));
        }
    } else {
#pragma unroll
        for (int mt = 0; mt < 2; mt++)
#pragma unroll
            for (int hh = 0; hh < 2; hh++) {
                int co = co0 + mbase + (mt << 4) + (lane >> 2) + (hh << 3);
                if (co < Cout) {
                    float bv = bias[co];
                    float* op = out + (size_t)(b * Cout + co) * HW + p0 + nbase + ((lane & 3) << 1);
#pragma unroll
                    for (int nt = 0; nt < NT; nt++) {
                        float2 v;
                        v.x = fmaxf(acc[mt][nt][hh * 2]     + bv, 0.f);
                        v.y = fmaxf(acc[mt][nt][hh * 2 + 1] + bv, 0.f);
                        *(float2*)(op + (nt << 3)) = v;
                    }
                }
            }
    }
}

// ---------------- fused segnorm-apply + bilinear up2 + NHWC bf16 split ---------
__global__ __launch_bounds__(256) void up2norm_kernel(
    const float* __restrict__ in, const float* __restrict__ stats,
    const int* __restrict__ seg, __nv_bfloat16* __restrict__ ph,
    __nv_bfloat16* __restrict__ pl, int C, int Hin, int Win, int cgN,
    int sh, float invHW)
{
    __shared__ float s[2][32][35];
    __shared__ float rs8[32][8], muR[32][8], Ksh[32];
    const int b = blockIdx.z / cgN, ci0 = (blockIdx.z % cgN) << 5;
    const int yo = blockIdx.y, xo0 = blockIdx.x << 6;
    const int Ho = Hin * 2, Wo = Win * 2;
    const int tid = threadIdx.y * 32 + threadIdx.x;

    {
        int ch = tid >> 3, k = tid & 7;
        int bc = b * C + ci0 + ch;
        float S = stats[bc * 16 + k * 2];
        float Q = stats[bc * 16 + k * 2 + 1];
        float mu = S * invHW;
        float var = Q * invHW - mu * mu;
        float r = rsqrtf(var + EPS_SN);
        rs8[ch][k] = r;
        muR[ch][k] = mu * r;
    }
    __syncthreads();
    if (tid < 32) {
        float K = 0.f;
#pragma unroll
        for (int k = 0; k < 8; k++) K += muR[tid][k];
        Ksh[tid] = K;
    }
    __syncthreads();

    int iy = yo >> 1, y0, y1;
    float wy0, wy1;
    if (yo & 1) { y0 = iy; y1 = min(iy + 1, Hin - 1); wy0 = .75f; wy1 = .25f; }
    else        { y0 = max(iy - 1, 0); y1 = iy;       wy0 = .25f; wy1 = .75f; }
    const int xin0 = xo0 >> 1;
    const int* sp = seg + b * 4096;
    for (int i = tid; i < 2176; i += 256) {
        int r = i / 1088, rem = i - r * 1088;
        int ch = rem / 34, col = rem - ch * 34;
        int gc = min(max(xin0 - 1 + col, 0), Win - 1);
        int gr = r ? y1 : y0;
        int cls = sp[((gr >> sh) << 6) + (gc >> sh)];
        float v = in[((size_t)(b * C + ci0 + ch) * Hin + gr) * Win + gc];
        s[r][ch][col] = v * rs8[ch][cls] - Ksh[ch];
    }
    __syncthreads();
    const int tx = threadIdx.x;
    const size_t obase = ((size_t)b * Ho + yo) * Wo;
#pragma unroll
    for (int k = 0; k < 8; k++) {
        int xo = xo0 + (k << 3) + threadIdx.y;
        int lx = (xo >> 1) - xin0;
        int ca, cb;
        float wa, wb;
        if (xo & 1) { ca = lx + 1; cb = lx + 2; wa = .75f; wb = .25f; }
        else        { ca = lx;     cb = lx + 1; wa = .25f; wb = .75f; }
        float v = wy0 * (wa * s[0][tx][ca] + wb * s[0][tx][cb])
                + wy1 * (wa * s[1][tx][ca] + wb * s[1][tx][cb]);
        __nv_bfloat16 h = __float2bfloat16(v);
        size_t a = (obase + xo) * C + ci0 + tx;
        ph[a] = h;
        pl[a] = __float2bfloat16(v - __bfloat162float(h));
    }
}

// ---------------- fp32 direct conv (final 64->3) -------------------------------
template<int CBT>
__global__ __launch_bounds__(256) void conv3x3_kernel(
    const float* __restrict__ in, const float* __restrict__ wgt,
    const float* __restrict__ bias, float* __restrict__ out,
    int Cin, int Cout, int H, int W, int tilesY, int doRelu)
{
    __shared__ __align__(16) float s_in[CCH][34][34];
    __shared__ __align__(16) float s_w[CCH][9][CBT];
    const int tx = threadIdx.x, ty = threadIdx.y;
    const int tid = ty * 32 + tx;
    const int tileY = blockIdx.y % tilesY;
    const int b = blockIdx.y / tilesY;
    const int co0 = blockIdx.z * CBT;
    const int x0 = blockIdx.x * 32, y0 = tileY * 32;
    float acc[PY][CBT];
#pragma unroll
    for (int p = 0; p < PY; p++)
#pragma unroll
        for (int j = 0; j < CBT; j++) acc[p][j] = 0.f;
    const float* inB = in + (size_t)b * Cin * H * W;
    for (int cin0 = 0; cin0 < Cin; cin0 += CCH) {
        __syncthreads();
        for (int i = tid; i < CCH * 1156; i += 256) {
            int ci = i / 1156, rem = i - ci * 1156;
            int r = rem / 34, c = rem - r * 34;
            int gr = y0 - 1 + r, gc = x0 - 1 + c;
            gr = (gr < 0) ? -gr : ((gr >= H) ? 2 * H - 2 - gr : gr);
            gc = (gc < 0) ? -gc : ((gc >= W) ? 2 * W - 2 - gc : gc);
            s_in[ci][r][c] = inB[(size_t)(cin0 + ci) * H * W + gr * W + gc];
        }
        for (int i = tid; i < CCH * 9 * CBT; i += 256) {
            int ci = i / (9 * CBT), rem = i - ci * (9 * CBT);
            int k = rem / CBT, j = rem - k * CBT;
            int co = co0 + j;
            s_w[ci][k][j] = (co < Cout) ? wgt[((size_t)co * Cin + cin0 + ci) * 9 + k] : 0.f;
        }
        __syncthreads();
#pragma unroll 1
        for (int ci = 0; ci < CCH; ci++) {
            float dp[6][3];
#pragma unroll
            for (int rr = 0; rr < 6; rr++)
#pragma unroll
                for (int c = 0; c < 3; c++) dp[rr][c] = s_in[ci][ty * PY + rr][tx + c];
#pragma unroll
            for (int kr = 0; kr < 3; kr++)
#pragma unroll
                for (int kc = 0; kc < 3; kc++) {
#pragma unroll
                    for (int p = 0; p < PY; p++) {
                        float d = dp[kr + p][kc];
#pragma unroll
                        for (int j = 0; j < CBT; j++)
                            acc[p][j] = fmaf(d, s_w[ci][kr * 3 + kc][j], acc[p][j]);
                    }
                }
        }
    }
    const int x = x0 + tx, yBase = y0 + ty * PY;
#pragma unroll
    for (int p = 0; p < PY; p++) {
        int y = yBase + p;
#pragma unroll
        for (int j = 0; j < CBT; j++) {
            int co = co0 + j;
            if (co < Cout) {
                float r = acc[p][j] + bias[co];
                if (doRelu) r = fmaxf(r, 0.f);
                out[((size_t)(b * Cout + co) * H + y) * W + x] = r;
            }
        }
    }
}

// ---------------- per-class instance-norm stats (float4 vectorized) ------------
__global__ __launch_bounds__(256) void segnorm_stats(
    const float* __restrict__ x, const int* __restrict__ seg,
    float* __restrict__ stats, int C, int HW, int logW, int sh)
{
    const int bc = blockIdx.x, b = bc / C;
    const float* xp = x + (size_t)bc * HW;
    const int* sp = seg + b * 4096;
    const int Wm1 = (1 << logW) - 1;
    float s[8] = {0}, q[8] = {0};
    for (int i0 = threadIdx.x << 2; i0 < HW; i0 += 1024) {
        float4 v4 = *(const float4*)(xp + i0);
        int h = i0 >> logW, wd = i0 & Wm1;   // 4 x-adjacent pixels, same row
        const int* srow = sp + ((h >> sh) << 6);
        int cls[4] = { srow[wd >> sh], srow[(wd + 1) >> sh],
                       srow[(wd + 2) >> sh], srow[(wd + 3) >> sh] };
        float vv[4] = { v4.x, v4.y, v4.z, v4.w };
#pragma unroll
        for (int e = 0; e < 4; e++) {
            float v = vv[e], v2 = v * v;
            int cl = cls[e];
#pragma unroll
            for (int k = 0; k < 8; k++)
                if (cl == k) { s[k] += v; q[k] += v2; }
        }
    }
#pragma unroll
    for (int k = 0; k < 8; k++)
#pragma unroll
        for (int o = 16; o > 0; o >>= 1) {
            s[k] += __shfl_xor_sync(0xffffffffu, s[k], o);
            q[k] += __shfl_xor_sync(0xffffffffu, q[k], o);
        }
    __shared__ float shs[8][8], shq[8][8];
    int warp = threadIdx.x >> 5, lane = threadIdx.x & 31;
    if (lane == 0)
#pragma unroll
        for (int k = 0; k < 8; k++) { shs[warp][k] = s[k]; shq[warp][k] = q[k]; }
    __syncthreads();
    if (threadIdx.x < 8) {
        float S = 0, Q = 0;
#pragma unroll
        for (int w = 0; w < 8; w++) { S += shs[w][threadIdx.x]; Q += shq[w][threadIdx.x]; }
        stats[bc * 16 + threadIdx.x * 2] = S;
        stats[bc * 16 + threadIdx.x * 2 + 1] = Q;
    }
}

// ---------------- host orchestration -------------------------------------------
static inline int ilog2i(int v) { int l = 0; while ((1 << l) < v) l++; return l; }

#define DSMEM_128 (2 * (2 * 128 * 128 + 32768) + 128)
#define DSMEM_64  (2 * (2 * 64 * 128 + 32768) + 128)

static void conv_mma(const __nv_bfloat16* pih, const __nv_bfloat16* pil,
                     const __nv_bfloat16* wh, const __nv_bfloat16* wl,
                     const float* bias, float* outF,
                     __nv_bfloat16* poh, __nv_bfloat16* pol, int mode,
                     int B, int Cin, int Cout, int H, int W) {
    int MT = (Cout > 64) ? 128 : 64;
    int Cpad = ((Cout + MT - 1) / MT) * MT;
    if (MT == 128)
        conv_mma_kernel<128><<<dim3((H * W) / 128, B, Cpad / 128), 256, DSMEM_128>>>(
            pih, pil, wh, wl, bias, outF, poh, pol, mode, Cin, Cout, H, W,
            ilog2i(W), ilog2i(Cin / 64));
    else
        conv_mma_kernel<64><<<dim3((H * W) / 128, B, Cpad / 64), 256, DSMEM_64>>>(
            pih, pil, wh, wl, bias, outF, poh, pol, mode, Cin, Cout, H, W,
            ilog2i(W), ilog2i(Cin / 64));
}

extern "C" void kernel_launch(void* const* d_in, const int* in_sizes, int n_in,
                              void* d_out, int out_size) {
    const float* x   = (const float*)d_in[0];
    const int*   seg = (const int*)  d_in[1];
    const float* W[8] = { (const float*)d_in[2],  (const float*)d_in[4],
                          (const float*)d_in[6],  (const float*)d_in[8],
                          (const float*)d_in[10], (const float*)d_in[12],
                          (const float*)d_in[14], (const float*)d_in[16] };
    const float* Bi[8] = { (const float*)d_in[3],  (const float*)d_in[5],
                           (const float*)d_in[7],  (const float*)d_in[9],
                           (const float*)d_in[11], (const float*)d_in[13],
                           (const float*)d_in[15], (const float*)d_in[17] };
    const float *wf = (const float*)d_in[18], *bf_ = (const float*)d_in[19];

    cudaFuncSetAttribute(conv_mma_kernel<128>,
                         cudaFuncAttributeMaxDynamicSharedMemorySize, DSMEM_128);
    cudaFuncSetAttribute(conv_mma_kernel<64>,
                         cudaFuncAttributeMaxDynamicSharedMemorySize, DSMEM_64);

    float *A, *Bb, *st;
    __nv_bfloat16 *p0h, *p0l, *p1h, *p1l, *wh, *wl;
    cudaGetSymbolAddress((void**)&A,   g_bufA);
    cudaGetSymbolAddress((void**)&Bb,  g_bufB);
    cudaGetSymbolAddress((void**)&st,  g_stats);
    cudaGetSymbolAddress((void**)&p0h, g_P0h);
    cudaGetSymbolAddress((void**)&p0l, g_P0l);
    cudaGetSymbolAddress((void**)&p1h, g_P1h);
    cudaGetSymbolAddress((void**)&p1l, g_P1l);
    cudaGetSymbolAddress((void**)&wh,  g_Wh);
    cudaGetSymbolAddress((void**)&wl,  g_Wl);

    const int CinA[8]  = {512, 256, 256, 256, 256, 128, 128, 64};
    const int CoutA[8] = {256, 256, 256, 256, 128, 128, 64,  64};
    long base[8];
    long off = 0;
    int CpadA[8], nA[8];
    for (int i = 0; i < 8; i++) {
        int MT = (CoutA[i] > 64) ? 128 : 64;
        CpadA[i] = ((CoutA[i] + MT - 1) / MT) * MT;
        nA[i] = 9 * CpadA[i] * CinA[i];
        base[i] = off;
        off += nA[i];
    }

    // launches 1+2: all-weight prep (activation-independent)
    for (int h = 0; h < 2; h++) {
        PrepArgs pa;
        int nmax = 0;
        for (int j = 0; j < 4; j++) {
            int i = h * 4 + j;
            pa.w[j] = W[i]; pa.base[j] = base[i];
            pa.Cout[j] = CoutA[i]; pa.Cpad[j] = CpadA[i];
            pa.Cin[j] = CinA[i]; pa.n[j] = nA[i];
            if (nA[i] > nmax) nmax = nA[i];
        }
        prep_all_kernel<<<dim3((nmax + 255) / 256, 4), 256>>>(pa, wh, wl);
    }

    // launch 3: input split; launch 4: conv1 (profiled by ncu)
    nchw_split_kernel<<<dim3(2, 64, 4 * 16), dim3(32, 8)>>>(x, p0h, p0l, 512, 64, 64, 16);
    conv_mma(p0h, p0l, wh + base[0], wl + base[0], Bi[0], A, 0, 0, 0, 4, 512, 256, 64, 64);
    segnorm_stats<<<4 * 256, 256>>>(A, seg, st, 256, 4096, 6, 0);
    up2norm_kernel<<<dim3(2, 128, 4 * 8), dim3(32, 8)>>>(A, st, seg, p1h, p1l,
                                                         256, 64, 64, 8, 0, 1.f / 4096.f);
    // stage 2 @ 128x128
    conv_mma(p1h, p1l, wh + base[1], wl + base[1], Bi[1], 0, p0h, p0l, 1, 4, 256, 256, 128, 128);
    conv_mma(p0h, p0l, wh + base[2], wl + base[2], Bi[2], 0, p1h, p1l, 1, 4, 256, 256, 128, 128);
    conv_mma(p1h, p1l, wh + base[3], wl + base[3], Bi[3], 0, p0h, p0l, 1, 4, 256, 256, 128, 128);
    conv_mma(p0h, p0l, wh + base[4], wl + base[4], Bi[4], A, 0, 0, 0, 4, 256, 128, 128, 128);
    segnorm_stats<<<4 * 128, 256>>>(A, seg, st, 128, 16384, 7, 1);
    up2norm_kernel<<<dim3(4, 256, 4 * 4), dim3(32, 8)>>>(A, st, seg, p1h, p1l,
                                                         128, 128, 128, 4, 1, 1.f / 16384.f);
    // stage 3 @ 256x256
    conv_mma(p1h, p1l, wh + base[5], wl + base[5], Bi[5], 0, p0h, p0l, 1, 4, 128, 128, 256, 256);
    conv_mma(p0h, p0l, wh + base[6], wl + base[6], Bi[6], A, 0, 0, 0, 4, 128, 64, 256, 256);
    segnorm_stats<<<4 * 64, 256>>>(A, seg, st, 64, 65536, 8, 2);
    up2norm_kernel<<<dim3(8, 512, 4 * 2), dim3(32, 8)>>>(A, st, seg, p1h, p1l,
                                                         64, 256, 256, 2, 2, 1.f / 65536.f);
    // stage 4 @ 512x512
    conv_mma(p1h, p1l, wh + base[7], wl + base[7], Bi[7], Bb, 0, 0, 0, 4, 64, 64, 512, 512);
    conv3x3_kernel<4><<<dim3(16, 16 * 4, 1), dim3(32, 8)>>>(
        Bb, wf, bf_, (float*)d_out, 64, 3, 512, 512, 16, 0);
}